// round 15
// baseline (speedup 1.0000x reference)
#include <cuda_runtime.h>

// chamfer_3DDist: B=16, N=M=4096.
// Output (float32): [dist1 (B*N) | dist2 (B*M) | idx1 (B*N) | idx2 (B*M)]
//
// Round-15: main-kernel flush path rework (finalize = measured-best R12 pair):
//  (1) conflict-free colpart layout (cl/ch planes; 33-stride) — the old u64
//      layout had a guaranteed 2-way bank conflict between query halves;
//  (2) single __syncwarp per unit (was 2);
//  (3) double-buffered DEFERRED flush: unit k flushes unit k-1's buffer, so
//      the STS->LDS dependency spans a whole unit of independent work.
// All distances / tie-break orders bit-identical to the reference.

#define BT    64
#define UQ    4
#define QT    256            // queries per block (BT*UQ)
#define CT    256            // candidates per block
#define NPTS  4096
#define BATCH 16
#define NQB   (NPTS / QT)    // 16
#define NCB   (NPTS / CT)    // 16
#define GRPC  16             // row-deferral group (cands)
#define QRNG  64             // queries per col partial
#define NPART (NPTS / QRNG)  // 64 col partials per batch
#define FLTMAX 3.402823466e38f

typedef unsigned long long u64;

// row partials per cand-block: (best value, group index as float)
__device__ float2 g_row[NCB][BATCH * NPTS];
// col partials: partial p covers queries [p*64, p*64+64) within the batch
__device__ float  g_col[NPART][BATCH * NPTS];
// merge selections: [0]=row winning group, [1]=col winning partial
__device__ int    g_sel[2][BATCH * NPTS];

__device__ __forceinline__ u64 pack2(float lo, float hi) {
    u64 r; asm("mov.b64 %0, {%1, %2};" : "=l"(r) : "f"(lo), "f"(hi)); return r;
}
__device__ __forceinline__ void unpack2(u64 v, float& lo, float& hi) {
    asm("mov.b64 {%0, %1}, %2;" : "=f"(lo), "=f"(hi) : "l"(v));
}
__device__ __forceinline__ u64 fma2(u64 a, u64 b, u64 c) {
    u64 d; asm("fma.rn.f32x2 %0, %1, %2, %3;" : "=l"(d) : "l"(a), "l"(b), "l"(c)); return d;
}
__device__ __forceinline__ u64 mul2(u64 a, u64 b) {
    u64 d; asm("mul.rn.f32x2 %0, %1, %2;" : "=l"(d) : "l"(a), "l"(b)); return d;
}
__device__ __forceinline__ u64 add2(u64 a, u64 b) {
    u64 d; asm("add.rn.f32x2 %0, %1, %2;" : "=l"(d) : "l"(a), "l"(b)); return d;
}

__device__ __forceinline__ float sqnorm_ref(float x, float y, float z) {
    return __fadd_rn(__fadd_rn(__fmul_rn(x, x), __fmul_rn(y, y)), __fmul_rn(z, z));
}
__device__ __forceinline__ float dist_ref(float qx, float qy, float qz, float q2,
                                          float cx, float cy, float cz, float c2) {
    float xy = __fmaf_rn(qz, cz, __fmaf_rn(qy, cy, __fmul_rn(qx, cx)));
    return __fmaf_rn(-2.0f, xy, __fadd_rn(q2, c2));
}

__global__ __launch_bounds__(BT, 8) void nn_main(
    const float* __restrict__ xyz1,
    const float* __restrict__ xyz2)
{
    const int cblk = blockIdx.x, qblk = blockIdx.y, b = blockIdx.z;
    const int tid = threadIdx.x, w = tid >> 5, lane = tid & 31;

    __shared__ float4 sc[CT / 2][2];
    // [warp][buf][pair j][h (lo/hi cand)][lane]; 33-stride + h-plane split
    // makes BOTH writer and flush-reader bank-conflict-free.
    __shared__ float colpart[2][2][8][2][33];
    __shared__ float2 rowst[QT];

    // stage candidates (xyz2), scaled by -2; norms from UNSCALED coords
    const float* cbase = xyz2 + (size_t)(b * NPTS + cblk * CT) * 3;
    for (int pp = tid; pp < CT / 2; pp += BT) {
        const float* p0 = cbase + 6 * pp;
        const float a0 = p0[0], a1 = p0[1], a2 = p0[2];
        const float b0 = p0[3], b1 = p0[4], b2 = p0[5];
        const float w0 = sqnorm_ref(a0, a1, a2);
        const float w1 = sqnorm_ref(b0, b1, b2);
        sc[pp][0] = make_float4(-2.0f * a0, -2.0f * b0, -2.0f * a1, -2.0f * b1);
        sc[pp][1] = make_float4(-2.0f * a2, -2.0f * b2, w0, w1);
    }

    // queries: thread owns 4 CONSECUTIVE queries (12 contiguous floats)
    u64 qx2[UQ], qy2[UQ], qz2[UQ], q22[UQ];
    float best[UQ], gacc[UQ], jgrp[UQ];
    {
        const int q0 = b * NPTS + qblk * QT + tid * UQ;
        const float4* qv = (const float4*)(xyz1 + 3 * q0);
        const float4 v0 = qv[0], v1 = qv[1], v2 = qv[2];
        const float qs[UQ][3] = {{v0.x, v0.y, v0.z}, {v0.w, v1.x, v1.y},
                                 {v1.z, v1.w, v2.x}, {v2.y, v2.z, v2.w}};
#pragma unroll
        for (int u = 0; u < UQ; ++u) {
            const float x0 = qs[u][0], x1 = qs[u][1], x2v = qs[u][2];
            const float s = sqnorm_ref(x0, x1, x2v);
            qx2[u] = pack2(x0, x0);
            qy2[u] = pack2(x1, x1);
            qz2[u] = pack2(x2v, x2v);
            q22[u] = pack2(s, s);
            best[u] = FLTMAX;
            gacc[u] = FLTMAX;
            jgrp[u] = 0.0f;
        }
    }
    __syncthreads();

    const ulonglong2* __restrict__ sp = (const ulonglong2*)sc;
    const int cand0 = b * NPTS + cblk * CT;
    const int fp = lane >> 2;          // flush: pair 0..7
    const int fs = (lane >> 1) & 1;    // flush: query half (64 queries)
    const int fh = lane & 1;           // flush: lo/hi cand of the pair

    for (int un = 0; un < CT / GRPC; ++un) {   // 16 units of 8 pairs
        const int buf = un & 1;

        // front-batch ALL candidate data for this unit (16 LDS.128 in flight)
        ulonglong2 c[16];
#pragma unroll
        for (int i = 0; i < 16; ++i) c[i] = sp[16 * un + i];

#pragma unroll
        for (int j = 0; j < 8; ++j) {
            const ulonglong2 A  = c[2 * j];      // (-2X pair, -2Y pair)
            const ulonglong2 Bv = c[2 * j + 1];  // (-2Z pair,  W pair)
            float cl, ch;
#pragma unroll
            for (int u = 0; u < UQ; ++u) {
                u64 t = fma2(qz2[u], Bv.x, fma2(qy2[u], A.y, mul2(qx2[u], A.x)));
                u64 d = add2(t, add2(q22[u], Bv.y));   // == fma(-2,xy,q2+c2)
                float dlo, dhi; unpack2(d, dlo, dhi);
                gacc[u] = fminf(gacc[u], fminf(dlo, dhi));
                if (u == 0) { cl = dlo; ch = dhi; }
                else        { cl = fminf(cl, dlo); ch = fminf(ch, dhi); }
            }
            colpart[w][buf][j][0][lane] = cl;
            colpart[w][buf][j][1][lane] = ch;
        }

        // row group commit (16 cands/group), ascending -> strict <
        const float gidx = (float)(cblk * (CT / GRPC) + un);
#pragma unroll
        for (int u = 0; u < UQ; ++u) {
            jgrp[u] = (gacc[u] < best[u]) ? gidx : jgrp[u];
            best[u] = fminf(best[u], gacc[u]);
            gacc[u] = FLTMAX;
        }

        __syncwarp();

        // deferred flush of the PREVIOUS unit's buffer (settled one unit ago)
        if (un > 0) {
            const float* fb = &colpart[w][buf ^ 1][fp][fh][0];
            float v = fb[fs * 16];
#pragma unroll
            for (int i = 1; i < 16; ++i)
                v = fminf(v, fb[fs * 16 + i]);
            g_col[qblk * 4 + w * 2 + fs][cand0 + 2 * ((un - 1) * 8 + fp) + fh] = v;
        }
    }

    // flush the last unit (data synced at the final in-loop __syncwarp)
    {
        const int lastbuf = ((CT / GRPC) - 1) & 1;
        const float* fb = &colpart[w][lastbuf][fp][fh][0];
        float v = fb[fs * 16];
#pragma unroll
        for (int i = 1; i < 16; ++i)
            v = fminf(v, fb[fs * 16 + i]);
        g_col[qblk * 4 + w * 2 + fs]
             [cand0 + 2 * (((CT / GRPC) - 1) * 8 + fp) + fh] = v;
    }

    // row epilogue: stage to smem, write coalesced
#pragma unroll
    for (int u = 0; u < UQ; ++u)
        rowst[tid * UQ + u] = make_float2(best[u], jgrp[u]);
    __syncthreads();
    {
        const int base = b * NPTS + qblk * QT;
        float2* __restrict__ gr = &g_row[cblk][base];
        for (int i = tid; i < QT; i += BT) gr[i] = rowst[i];
    }
}

// Phase A: thread-per-element merge, fully coalesced. Ascending scan with
// strict < keeps the EARLIEST tying partial (exact first-occurrence).
__global__ __launch_bounds__(256) void nn_merge(float* __restrict__ out)
{
    const int t  = blockIdx.x * blockDim.x + threadIdx.x;   // [0, 2*BN)
    const int BN = BATCH * NPTS;

    if (t < BN) {
        const int qg = t;
        float2 r = g_row[0][qg];
        float bv = r.x, bg = r.y;
#pragma unroll
        for (int cb = 1; cb < NCB; ++cb) {
            const float2 rr = g_row[cb][qg];
            const bool tk = rr.x < bv;
            bv = tk ? rr.x : bv;
            bg = tk ? rr.y : bg;
        }
        out[qg] = bv;
        g_sel[0][qg] = (int)bg;
    } else {
        const int mg = t - BN;
        float bv = g_col[0][mg];
        int   bp = 0;
#pragma unroll 16
        for (int p = 1; p < NPART; ++p) {
            const float v = g_col[p][mg];
            const bool tk = v < bv;
            bv = tk ? v : bv;
            bp = tk ? p : bp;
        }
        out[BN + mg] = bv;
        g_sel[1][mg] = bp;
    }
}

// Phase B: warp-per-element rescan. Recomputes distances bit-identically in
// the winning group/range and takes the LOWEST matching global index.
__global__ __launch_bounds__(256) void nn_rescan(
    const float* __restrict__ xyz1,
    const float* __restrict__ xyz2,
    float* __restrict__ out)
{
    const int BN   = BATCH * NPTS;
    const int gw   = blockIdx.x * (blockDim.x >> 5) + (threadIdx.x >> 5);
    const int lane = threadIdx.x & 31;

    if (gw < BN) {
        // row: idx1 for query qg
        const int qg = gw;
        const int b  = qg >> 12;            // /NPTS
        const float bv = out[qg];
        const int base = g_sel[0][qg] * GRPC;

        const float* qp = xyz1 + 3 * qg;
        const float qx = qp[0], qy = qp[1], qz = qp[2];
        const float q2 = sqnorm_ref(qx, qy, qz);

        int found = 0x7fffffff;
        if (lane < GRPC) {
            const float* cp = xyz2 + (size_t)b * NPTS * 3 + 3 * (base + lane);
            const float c2 = sqnorm_ref(cp[0], cp[1], cp[2]);
            const float d = dist_ref(qx, qy, qz, q2, cp[0], cp[1], cp[2], c2);
            if (d == bv) found = base + lane;
        }
#pragma unroll
        for (int off = 16; off >= 1; off >>= 1)
            found = min(found, __shfl_xor_sync(0xffffffffu, found, off));

        if (lane == 0) out[2 * BN + qg] = (float)found;
    } else {
        // col: idx2 for candidate mg
        const int mg = gw - BN;
        const int b  = mg >> 12;
        const float bv = out[BN + mg];
        const int   bp = g_sel[1][mg];      // queries [bp*64, bp*64+64)

        const float* cp = xyz2 + 3 * mg;
        const float cx = cp[0], cy = cp[1], cz = cp[2];
        const float c2 = sqnorm_ref(cx, cy, cz);

        // rescan: lane l -> queries bp*64 + 2l + {0,1}, coalesced float2
        const int qn0 = b * NPTS + bp * QRNG + lane * 2;
        const float2* qv = (const float2*)(xyz1 + 3 * qn0);  // 8B aligned
        const float2 v0 = qv[0], v1 = qv[1], v2 = qv[2];
        const float qs[2][3] = {{v0.x, v0.y, v1.x}, {v1.y, v2.x, v2.y}};
        int found = 0x7fffffff;
#pragma unroll
        for (int k = 1; k >= 0; --k) {
            const float q2n = sqnorm_ref(qs[k][0], qs[k][1], qs[k][2]);
            const float d = dist_ref(qs[k][0], qs[k][1], qs[k][2], q2n,
                                     cx, cy, cz, c2);
            if (d == bv) found = bp * QRNG + lane * 2 + k;
        }
#pragma unroll
        for (int off = 16; off >= 1; off >>= 1)
            found = min(found, __shfl_xor_sync(0xffffffffu, found, off));

        if (lane == 0) out[3 * BN + mg] = (float)found;
    }
}

extern "C" void kernel_launch(void* const* d_in, const int* in_sizes, int n_in,
                              void* d_out, int out_size)
{
    (void)in_sizes; (void)n_in; (void)out_size;
    const float* xyz1 = (const float*)d_in[0];
    const float* xyz2 = (const float*)d_in[1];
    float* out = (float*)d_out;

    dim3 grid(NCB, NQB, BATCH);   // (16, 16, 16) = 4096 blocks
    nn_main<<<grid, BT>>>(xyz1, xyz2);

    const int BN = BATCH * NPTS;
    nn_merge<<<(2 * BN) / 256, 256>>>(out);
    nn_rescan<<<(2 * BN * 32) / 256, 256>>>(xyz1, xyz2, out);
}

// round 16
// speedup vs baseline: 1.0506x; 1.0506x over previous
#include <cuda_runtime.h>

// chamfer_3DDist: B=16, N=M=4096.
// Output (float32): [dist1 (B*N) | dist2 (B*M) | idx1 (B*N) | idx2 (B*M)]
//
// Round-16: deterministic packed-u64 atomicMin replaces all scratch + merge.
//  key = (monotone_bits(d) << 32) | partial_id  -> atomicMin picks min d,
//  then smallest partial id on ties == exact first-occurrence at group
//  granularity (min is associative/commutative -> order-independent result).
//  Main body is the measured-best R14 kernel; only output paths changed.
//  Rescan decodes d bit-exactly and resolves the exact lowest matching index.

#define BT    64
#define UQ    4
#define QT    256            // queries per block (BT*UQ)
#define CT    256            // candidates per block
#define NPTS  4096
#define BATCH 16
#define NQB   (NPTS / QT)    // 16
#define NCB   (NPTS / CT)    // 16
#define GRPC  16             // row-deferral group (cands)
#define QRNG  64             // queries per col partial
#define FLTMAX 3.402823466e38f

typedef unsigned long long u64;
typedef unsigned int u32;

// packed (dkey, partial) results: [0]=rows (dist1), [1]=cols (dist2)
__device__ u64 g_key[2][BATCH * NPTS];

__device__ __forceinline__ u64 pack2(float lo, float hi) {
    u64 r; asm("mov.b64 %0, {%1, %2};" : "=l"(r) : "f"(lo), "f"(hi)); return r;
}
__device__ __forceinline__ void unpack2(u64 v, float& lo, float& hi) {
    asm("mov.b64 {%0, %1}, %2;" : "=f"(lo), "=f"(hi) : "l"(v));
}
__device__ __forceinline__ u64 fma2(u64 a, u64 b, u64 c) {
    u64 d; asm("fma.rn.f32x2 %0, %1, %2, %3;" : "=l"(d) : "l"(a), "l"(b), "l"(c)); return d;
}
__device__ __forceinline__ u64 mul2(u64 a, u64 b) {
    u64 d; asm("mul.rn.f32x2 %0, %1, %2;" : "=l"(d) : "l"(a), "l"(b)); return d;
}
__device__ __forceinline__ u64 add2(u64 a, u64 b) {
    u64 d; asm("add.rn.f32x2 %0, %1, %2;" : "=l"(d) : "l"(a), "l"(b)); return d;
}

// monotone float<->u32 (unsigned order == float order)
__device__ __forceinline__ u32 fenc(float f) {
    u32 b = __float_as_uint(f);
    return (b & 0x80000000u) ? ~b : (b | 0x80000000u);
}
__device__ __forceinline__ float fdec(u32 k) {
    u32 b = (k & 0x80000000u) ? (k ^ 0x80000000u) : ~k;
    return __uint_as_float(b);
}

__device__ __forceinline__ float sqnorm_ref(float x, float y, float z) {
    return __fadd_rn(__fadd_rn(__fmul_rn(x, x), __fmul_rn(y, y)), __fmul_rn(z, z));
}
__device__ __forceinline__ float dist_ref(float qx, float qy, float qz, float q2,
                                          float cx, float cy, float cz, float c2) {
    float xy = __fmaf_rn(qz, cz, __fmaf_rn(qy, cy, __fmul_rn(qx, cx)));
    return __fmaf_rn(-2.0f, xy, __fadd_rn(q2, c2));
}

__global__ __launch_bounds__(512) void nn_init()
{
    const int t = blockIdx.x * blockDim.x + threadIdx.x;
    ((u64*)g_key)[t] = ~0ull;
}

__global__ __launch_bounds__(BT, 8) void nn_main(
    const float* __restrict__ xyz1,
    const float* __restrict__ xyz2)
{
    const int cblk = blockIdx.x, qblk = blockIdx.y, b = blockIdx.z;
    const int tid = threadIdx.x, w = tid >> 5, lane = tid & 31;

    __shared__ float4 sc[CT / 2][2];
    __shared__ u64 colpart[2][8][33];

    // stage candidates (xyz2), scaled by -2; norms from UNSCALED coords
    const float* cbase = xyz2 + (size_t)(b * NPTS + cblk * CT) * 3;
    for (int pp = tid; pp < CT / 2; pp += BT) {
        const float* p0 = cbase + 6 * pp;
        const float a0 = p0[0], a1 = p0[1], a2 = p0[2];
        const float b0 = p0[3], b1 = p0[4], b2 = p0[5];
        const float w0 = sqnorm_ref(a0, a1, a2);
        const float w1 = sqnorm_ref(b0, b1, b2);
        sc[pp][0] = make_float4(-2.0f * a0, -2.0f * b0, -2.0f * a1, -2.0f * b1);
        sc[pp][1] = make_float4(-2.0f * a2, -2.0f * b2, w0, w1);
    }

    // queries: thread owns 4 CONSECUTIVE queries (12 contiguous floats)
    u64 qx2[UQ], qy2[UQ], qz2[UQ], q22[UQ];
    float best[UQ], gacc[UQ];
    int   jgrp[UQ];
    const int q0 = b * NPTS + qblk * QT + tid * UQ;
    {
        const float4* qv = (const float4*)(xyz1 + 3 * q0);
        const float4 v0 = qv[0], v1 = qv[1], v2 = qv[2];
        const float qs[UQ][3] = {{v0.x, v0.y, v0.z}, {v0.w, v1.x, v1.y},
                                 {v1.z, v1.w, v2.x}, {v2.y, v2.z, v2.w}};
#pragma unroll
        for (int u = 0; u < UQ; ++u) {
            const float x0 = qs[u][0], x1 = qs[u][1], x2v = qs[u][2];
            const float s = sqnorm_ref(x0, x1, x2v);
            qx2[u] = pack2(x0, x0);
            qy2[u] = pack2(x1, x1);
            qz2[u] = pack2(x2v, x2v);
            q22[u] = pack2(s, s);
            best[u] = FLTMAX;
            gacc[u] = FLTMAX;
            jgrp[u] = 0;
        }
    }
    __syncthreads();

    const ulonglong2* __restrict__ sp = (const ulonglong2*)sc;
    const int cand0 = b * NPTS + cblk * CT;

    for (int k8 = 0; k8 < CT / 2; k8 += 8) {
        // front-batch ALL candidate data for this unit (16 LDS.128 in flight)
        ulonglong2 c[16];
#pragma unroll
        for (int i = 0; i < 16; ++i) c[i] = sp[2 * k8 + i];

#pragma unroll
        for (int j = 0; j < 8; ++j) {
            const ulonglong2 A  = c[2 * j];      // (-2X pair, -2Y pair)
            const ulonglong2 Bv = c[2 * j + 1];  // (-2Z pair,  W pair)
            float cl, ch;
#pragma unroll
            for (int u = 0; u < UQ; ++u) {
                u64 t = fma2(qz2[u], Bv.x, fma2(qy2[u], A.y, mul2(qx2[u], A.x)));
                u64 d = add2(t, add2(q22[u], Bv.y));   // == fma(-2,xy,q2+c2)
                float dlo, dhi; unpack2(d, dlo, dhi);
                gacc[u] = fminf(gacc[u], fminf(dlo, dhi));
                if (u == 0) { cl = dlo; ch = dhi; }
                else        { cl = fminf(cl, dlo); ch = fminf(ch, dhi); }
            }
            colpart[w][j][lane] = pack2(cl, ch);
        }

        // row group commit (16 cands/group), ascending -> strict <
        const int gidx = cblk * (CT / GRPC) + (k8 >> 3);
#pragma unroll
        for (int u = 0; u < UQ; ++u) {
            jgrp[u] = (gacc[u] < best[u]) ? gidx : jgrp[u];
            best[u] = fminf(best[u], gacc[u]);
            gacc[u] = FLTMAX;
        }

        // col flush: 32 reductions (8 pairs x 2 query-halves x 2 cands);
        // packed (dkey, partial) atomicMin -> deterministic, exact tie order
        __syncwarp();
        {
            const int p = lane >> 2;          // pair 0..7
            const int s = (lane >> 1) & 1;    // query half (64 queries)
            const int h = lane & 1;           // lo/hi cand of the pair
            const float* fb = (const float*)colpart[w][p];
            float v = fb[(s * 16) * 2 + h];
#pragma unroll
            for (int i = 1; i < 16; ++i)
                v = fminf(v, fb[(s * 16 + i) * 2 + h]);
            const u64 key = ((u64)fenc(v) << 32) | (u32)(qblk * 4 + w * 2 + s);
            atomicMin(&g_key[1][cand0 + 2 * (k8 + p) + h], key);
        }
        __syncwarp();
    }

    // row epilogue: one packed atomicMin per owned query
#pragma unroll
    for (int u = 0; u < UQ; ++u) {
        const u64 key = ((u64)fenc(best[u]) << 32) | (u32)jgrp[u];
        atomicMin(&g_key[0][q0 + u], key);
    }
}

// Rescan: warp per element. Decode (bv, sel) from the packed key, recompute
// distances bit-identically in the winning group/range, take the LOWEST
// matching global index (== exact first-occurrence argmin). Writes dist+idx.
__global__ __launch_bounds__(256) void nn_rescan(
    const float* __restrict__ xyz1,
    const float* __restrict__ xyz2,
    float* __restrict__ out)
{
    const int BN   = BATCH * NPTS;
    const int gw   = blockIdx.x * (blockDim.x >> 5) + (threadIdx.x >> 5);
    const int lane = threadIdx.x & 31;

    if (gw < BN) {
        // row: dist1/idx1 for query qg
        const int qg = gw;
        const int b  = qg >> 12;            // /NPTS
        const u64 key = g_key[0][qg];
        const float bv = fdec((u32)(key >> 32));
        const int base = (int)(key & 0xffffffffu) * GRPC;

        const float* qp = xyz1 + 3 * qg;
        const float qx = qp[0], qy = qp[1], qz = qp[2];
        const float q2 = sqnorm_ref(qx, qy, qz);

        int found = 0x7fffffff;
        if (lane < GRPC) {
            const float* cp = xyz2 + (size_t)b * NPTS * 3 + 3 * (base + lane);
            const float c2 = sqnorm_ref(cp[0], cp[1], cp[2]);
            const float d = dist_ref(qx, qy, qz, q2, cp[0], cp[1], cp[2], c2);
            if (d == bv) found = base + lane;
        }
#pragma unroll
        for (int off = 16; off >= 1; off >>= 1)
            found = min(found, __shfl_xor_sync(0xffffffffu, found, off));

        if (lane == 0) {
            out[qg]          = bv;
            out[2 * BN + qg] = (float)found;
        }
    } else {
        // col: dist2/idx2 for candidate mg
        const int mg = gw - BN;
        const int b  = mg >> 12;
        const u64 key = g_key[1][mg];
        const float bv = fdec((u32)(key >> 32));
        const int   bp = (int)(key & 0xffffffffu);   // queries [bp*64, +64)

        const float* cp = xyz2 + 3 * mg;
        const float cx = cp[0], cy = cp[1], cz = cp[2];
        const float c2 = sqnorm_ref(cx, cy, cz);

        // rescan: lane l -> queries bp*64 + 2l + {0,1}, coalesced float2
        const int qn0 = b * NPTS + bp * QRNG + lane * 2;
        const float2* qv = (const float2*)(xyz1 + 3 * qn0);  // 8B aligned
        const float2 v0 = qv[0], v1 = qv[1], v2 = qv[2];
        const float qs[2][3] = {{v0.x, v0.y, v1.x}, {v1.y, v2.x, v2.y}};
        int found = 0x7fffffff;
#pragma unroll
        for (int k = 1; k >= 0; --k) {
            const float q2n = sqnorm_ref(qs[k][0], qs[k][1], qs[k][2]);
            const float d = dist_ref(qs[k][0], qs[k][1], qs[k][2], q2n,
                                     cx, cy, cz, c2);
            if (d == bv) found = bp * QRNG + lane * 2 + k;
        }
#pragma unroll
        for (int off = 16; off >= 1; off >>= 1)
            found = min(found, __shfl_xor_sync(0xffffffffu, found, off));

        if (lane == 0) {
            out[BN + mg]     = bv;
            out[3 * BN + mg] = (float)found;
        }
    }
}

extern "C" void kernel_launch(void* const* d_in, const int* in_sizes, int n_in,
                              void* d_out, int out_size)
{
    (void)in_sizes; (void)n_in; (void)out_size;
    const float* xyz1 = (const float*)d_in[0];
    const float* xyz2 = (const float*)d_in[1];
    float* out = (float*)d_out;

    const int BN = BATCH * NPTS;
    nn_init<<<(2 * BN) / 512, 512>>>();

    dim3 grid(NCB, NQB, BATCH);   // (16, 16, 16) = 4096 blocks
    nn_main<<<grid, BT>>>(xyz1, xyz2);

    nn_rescan<<<(2 * BN * 32) / 256, 256>>>(xyz1, xyz2, out);
}